// round 14
// baseline (speedup 1.0000x reference)
#include <cuda_runtime.h>
#include <cstdint>

// Spiking-neuron K=16 scan as a 4-byte LUT with NaN-boxed exception records.
//
// z_t = ((v-T)/(|v|+1) > 0) == (v > T) since denom >= 1. Given the spike
// pattern, out = sum z_t*d_t is a constant; the pattern is a piecewise-
// constant function of v0 = |x| (endpoint-agreement + monotone induction).
//
// val[4096]: clean cell -> exact output (4B LDS, hot path).
//            transition cell -> NaN-boxed index into rec[].
// rec[1024]: {brk, oLo, oHi} exact split (bisected on float bits, each half
//            re-verified by endpoint agreement). rec[0] = {0, NaN, NaN} is the
//            "run the exact scan" marker (multi-transition / overflow; ~never).

#define NCELL 4096
#define NREC  1024

#define H_LIST {-0.00285825f, 0.09859432f, 0.07954306f, 0.08560576f, 0.0910411f, 0.10557652f, \
                0.04608637f, 0.07096123f, 0.01989892f, 0.03412642f, 0.03321506f, 0.01300904f, \
                -0.02348068f, 0.06102338f, -0.00509757f, 0.00051896f}
#define D_LIST {0.04908372f, -0.00948576f, 0.00083943f, 0.07961489f, 0.08128168f, 0.02395899f, \
                0.05197346f, 0.01595683f, 0.02185501f, 0.01893722f, 0.0074682f, -0.00088913f, \
                0.01660369f, 0.00298292f, 0.0071363f, 0.00279426f}
#define T_LIST {0.20153396f, -0.01304637f, -0.19541621f, 0.19903184f, 0.1529713f, -0.00479887f, \
                0.07102165f, 0.02109929f, 0.01368383f, -0.00360851f, -0.01454873f, -0.03991705f, \
                -0.00440092f, -0.06122432f, -0.02989412f, -0.04975629f}

__device__ __align__(16) float  g_val[NCELL];
__device__ __align__(16) float4 g_rec[NREC];
__device__ int g_cnt;

// Exact scan, reference op order. 'one' == 1.0f runtime param keeps FFMA form.
static __device__ __forceinline__ float snn_scan(float v0, float one) {
    constexpr float Hc[16] = H_LIST;
    constexpr float Dc[16] = D_LIST;
    constexpr float Tc[16] = T_LIST;
    float v = v0, o = 0.0f;
#pragma unroll
    for (int t = 0; t < 15; t++) {
        if (v > Tc[t]) {
            o = fmaf(one, Dc[t], o);
            v = fmaf(one, -Hc[t + 1], v);
        }
    }
    if (v > Tc[15]) o = fmaf(one, Dc[15], o);
    return o;
}

static __device__ __forceinline__ uint32_t snn_pat(float v0, float one, float* oOut) {
    constexpr float Hc[16] = H_LIST;
    constexpr float Dc[16] = D_LIST;
    constexpr float Tc[16] = T_LIST;
    float v = v0, o = 0.0f;
    uint32_t pat = 0;
#pragma unroll
    for (int t = 0; t < 16; t++) {
        bool z = v > Tc[t];
        pat |= (uint32_t)z << t;
        if (z) {
            o = fmaf(one, Dc[t], o);
            if (t < 15) v = fmaf(one, -Hc[t + 1], v);
        }
    }
    *oOut = o;
    return pat;
}

__global__ void init_table() {
    if (threadIdx.x == 0) {
        g_cnt = 1;
        float qnan = __int_as_float(0x7FC00000);
        g_rec[0] = make_float4(0.0f, qnan, qnan, 0.0f);
    }
}

__global__ void build_table(float one) {
    int k = blockIdx.x * blockDim.x + threadIdx.x;
    if (k >= NCELL) return;

    float lo = (float)k * 0x1p-12f;  // exact
    float hi;
    if (k == NCELL - 1) {
        hi = 3.0e38f;  // top cell extends upward (idx clamped in main)
    } else {
        float e = (float)(k + 1) * 0x1p-12f;
        hi = __int_as_float(__float_as_int(e) - 1);  // nextdown
    }

    float oLo, oHi;
    uint32_t pl = snn_pat(lo, one, &oLo);
    uint32_t ph = snn_pat(hi, one, &oHi);

    if (pl == ph) {
        g_val[k] = oLo;  // uniform cell: exact
        return;
    }

    // Bisect the transition on positive-float bit order (exact scans).
    uint32_t a = __float_as_uint(lo), c = __float_as_uint(hi);
    while (c - a > 1u) {
        uint32_t m = a + (c - a) / 2u;
        float om;
        uint32_t pm = snn_pat(__uint_as_float(m), one, &om);
        if (pm == pl) a = m; else c = m;
    }
    float b = __uint_as_float(a), bp = __uint_as_float(c);
    float ob, obp;
    uint32_t pb = snn_pat(b, one, &ob);
    uint32_t pbp = snn_pat(bp, one, &obp);

    int r = 0;  // rec 0 = scan-fallback marker
    if (pb == pl && pbp == ph) {
        // [lo,b] uniform (oLo), [bp,hi] uniform (oHi): exact split record.
        int slot = atomicAdd(&g_cnt, 1);
        if (slot < NREC) {
            g_rec[slot] = make_float4(b, oLo, oHi, 0.0f);
            r = slot;
        }
    }
    g_val[k] = __int_as_float(0x7FC00000u | (uint32_t)r);  // NaN-boxed index
}

static __device__ __forceinline__ float lut_val(float xv, const float* tbl,
                                                const float4* recs, bool* bad) {
    float v0 = fabsf(xv);
    int idx = (int)(v0 * 4096.0f);   // exact (power-of-two scale)
    idx = min(idx, NCELL - 1);
    float val = tbl[idx];
    if (!(val == val)) {             // rare second level (~1.5% of lanes)
        uint32_t r = __float_as_uint(val) & (NREC - 1);
        float4 rec = recs[r];
        val = (v0 > rec.x) ? rec.z : rec.y;
        *bad |= !(val == val);       // rec 0 -> still NaN -> exact scan
    }
    return val;
}

static __device__ __forceinline__ float finish(float xv, float val) {
    // out = val * sign(x): XOR sign bit; exact 0 for x == 0.
    uint32_t rb = __float_as_uint(val) ^ (__float_as_uint(xv) & 0x80000000u);
    return (xv == 0.0f) ? 0.0f : __uint_as_float(rb);
}

__global__ void __launch_bounds__(256) Squre02_kernel(const float* __restrict__ x,
                                                      float* __restrict__ y, int n,
                                                      float one) {
    __shared__ __align__(16) float  tbl[NCELL];
    __shared__ __align__(16) float4 recs[NREC];
    {
        const float4* src = (const float4*)g_val;
        float4* dst = (float4*)tbl;
#pragma unroll
        for (int i = threadIdx.x; i < NCELL / 4; i += 256) dst[i] = src[i];
#pragma unroll
        for (int i = threadIdx.x; i < NREC; i += 256) recs[i] = g_rec[i];
    }
    __syncthreads();

    const int tid = blockIdx.x * blockDim.x + threadIdx.x;
    const int nthreads = gridDim.x * blockDim.x;
    const int n4 = n >> 2;
    const float4* __restrict__ x4 = (const float4*)x;
    float4* __restrict__ y4 = (float4*)y;

    for (int i = tid; i < n4; i += 2 * nthreads) {
        const int i2 = i + nthreads;
        const bool has2 = (i2 < n4);
        float4 a = __ldcs(&x4[i]);
        float4 b = has2 ? __ldcs(&x4[i2]) : make_float4(0.f, 0.f, 0.f, 0.f);

        bool bad = false;
        float va0 = lut_val(a.x, tbl, recs, &bad);
        float va1 = lut_val(a.y, tbl, recs, &bad);
        float va2 = lut_val(a.z, tbl, recs, &bad);
        float va3 = lut_val(a.w, tbl, recs, &bad);
        float vb0 = lut_val(b.x, tbl, recs, &bad);
        float vb1 = lut_val(b.y, tbl, recs, &bad);
        float vb2 = lut_val(b.z, tbl, recs, &bad);
        float vb3 = lut_val(b.w, tbl, recs, &bad);

        // Exact-scan fallback: only rec-0 hits (multi-transition/overflow), ~never.
        if (__ballot_sync(__activemask(), bad)) {
            if (!(va0 == va0)) va0 = snn_scan(fabsf(a.x), one);
            if (!(va1 == va1)) va1 = snn_scan(fabsf(a.y), one);
            if (!(va2 == va2)) va2 = snn_scan(fabsf(a.z), one);
            if (!(va3 == va3)) va3 = snn_scan(fabsf(a.w), one);
            if (!(vb0 == vb0)) vb0 = snn_scan(fabsf(b.x), one);
            if (!(vb1 == vb1)) vb1 = snn_scan(fabsf(b.y), one);
            if (!(vb2 == vb2)) vb2 = snn_scan(fabsf(b.z), one);
            if (!(vb3 == vb3)) vb3 = snn_scan(fabsf(b.w), one);
        }

        float4 ra, rb;
        ra.x = finish(a.x, va0);
        ra.y = finish(a.y, va1);
        ra.z = finish(a.z, va2);
        ra.w = finish(a.w, va3);
        rb.x = finish(b.x, vb0);
        rb.y = finish(b.y, vb1);
        rb.z = finish(b.z, vb2);
        rb.w = finish(b.w, vb3);

        __stcs(&y4[i], ra);
        if (has2) __stcs(&y4[i2], rb);
    }

    // Scalar tail (not hit for this shape).
    for (int j = (n4 << 2) + tid; j < n; j += nthreads) {
        bool bad = false;
        float v = lut_val(x[j], tbl, recs, &bad);
        if (!(v == v)) v = snn_scan(fabsf(x[j]), one);
        y[j] = finish(x[j], v);
    }
}

extern "C" void kernel_launch(void* const* d_in, const int* in_sizes, int n_in,
                              void* d_out, int out_size) {
    const float* x = (const float*)d_in[0];
    for (int i = 0; i < n_in; i++) {
        if (in_sizes[i] == out_size) { x = (const float*)d_in[i]; break; }
    }
    float* y = (float*)d_out;
    const int n = out_size;

    init_table<<<1, 32>>>();
    build_table<<<NCELL / 256, 256>>>(1.0f);
    // 148 SMs x 7 CTAs (smem 32KB/CTA): balanced grid-stride.
    Squre02_kernel<<<1036, 256>>>(x, y, n, 1.0f);
}

// round 15
// speedup vs baseline: 1.0349x; 1.0349x over previous
#include <cuda_runtime.h>
#include <cstdint>

// Spiking-neuron K=16 scan as a 4-byte LUT over v0 in [0,4), with NaN-boxed
// exception records for transition cells.
//
// z_t = ((v-T)/(|v|+1) > 0) == (v > T) since denom >= 1. Given the spike
// pattern, out = sum z_t*d_t is a constant; the pattern is a piecewise-
// constant function of v0 = |x| (endpoint-agreement + monotone induction).
// For v0 >= ~1.2 the pattern is constant (all ones), so the top cell
// [4, 3e38] verifies clean -> the table now covers ALL of the mass (prior
// rounds clamped |x|>=1 -> 32% of elements into the slow path; fixed here).
//
// val[8192] over [0,4) at 2^-11: clean cell -> exact output (4B LDS hot path)
//                                transition -> NaN-boxed index into rec[].
// rec[256]: {brk, oLo, oHi} exact split (float-bit bisection, both halves
//           re-verified). rec[0] = {0,NaN,NaN} = run-exact-scan marker
//           (multi-transition cell or record overflow; ~never).

#define NCELL 8192
#define NREC  256

#define H_LIST {-0.00285825f, 0.09859432f, 0.07954306f, 0.08560576f, 0.0910411f, 0.10557652f, \
                0.04608637f, 0.07096123f, 0.01989892f, 0.03412642f, 0.03321506f, 0.01300904f, \
                -0.02348068f, 0.06102338f, -0.00509757f, 0.00051896f}
#define D_LIST {0.04908372f, -0.00948576f, 0.00083943f, 0.07961489f, 0.08128168f, 0.02395899f, \
                0.05197346f, 0.01595683f, 0.02185501f, 0.01893722f, 0.0074682f, -0.00088913f, \
                0.01660369f, 0.00298292f, 0.0071363f, 0.00279426f}
#define T_LIST {0.20153396f, -0.01304637f, -0.19541621f, 0.19903184f, 0.1529713f, -0.00479887f, \
                0.07102165f, 0.02109929f, 0.01368383f, -0.00360851f, -0.01454873f, -0.03991705f, \
                -0.00440092f, -0.06122432f, -0.02989412f, -0.04975629f}

__device__ __align__(16) float  g_val[NCELL];
__device__ __align__(16) float4 g_rec[NREC];

// Exact scan, reference op order. 'one' == 1.0f runtime param keeps FFMA form.
static __device__ __forceinline__ float snn_scan(float v0, float one) {
    constexpr float Hc[16] = H_LIST;
    constexpr float Dc[16] = D_LIST;
    constexpr float Tc[16] = T_LIST;
    float v = v0, o = 0.0f;
#pragma unroll
    for (int t = 0; t < 15; t++) {
        if (v > Tc[t]) {
            o = fmaf(one, Dc[t], o);
            v = fmaf(one, -Hc[t + 1], v);
        }
    }
    if (v > Tc[15]) o = fmaf(one, Dc[15], o);
    return o;
}

static __device__ __forceinline__ uint32_t snn_pat(float v0, float one, float* oOut) {
    constexpr float Hc[16] = H_LIST;
    constexpr float Dc[16] = D_LIST;
    constexpr float Tc[16] = T_LIST;
    float v = v0, o = 0.0f;
    uint32_t pat = 0;
#pragma unroll
    for (int t = 0; t < 16; t++) {
        bool z = v > Tc[t];
        pat |= (uint32_t)z << t;
        if (z) {
            o = fmaf(one, Dc[t], o);
            if (t < 15) v = fmaf(one, -Hc[t + 1], v);
        }
    }
    *oOut = o;
    return pat;
}

// Single-block builder: smem record counter, no separate init launch.
__global__ void __launch_bounds__(1024) build_table(float one) {
    __shared__ int s_cnt;
    if (threadIdx.x == 0) {
        s_cnt = 1;
        float qnan = __int_as_float(0x7FC00000);
        g_rec[0] = make_float4(0.0f, qnan, qnan, 0.0f);
    }
    __syncthreads();

    for (int k = threadIdx.x; k < NCELL; k += 1024) {
        float lo = (float)k * 0x1p-11f;                    // exact
        float hi;
        if (k == NCELL - 1) {
            hi = 3.0e38f;                                  // top cell reaches up
        } else {
            float e = (float)(k + 1) * 0x1p-11f;
            hi = __int_as_float(__float_as_int(e) - 1);    // nextdown
        }

        float oLo, oHi;
        uint32_t pl = snn_pat(lo, one, &oLo);
        uint32_t ph = snn_pat(hi, one, &oHi);

        if (pl == ph) {
            g_val[k] = oLo;                                // uniform: exact
            continue;
        }

        // Bisect the transition on positive-float bit order (exact scans).
        uint32_t a = __float_as_uint(lo), c = __float_as_uint(hi);
        while (c - a > 1u) {
            uint32_t m = a + (c - a) / 2u;
            float om;
            uint32_t pm = snn_pat(__uint_as_float(m), one, &om);
            if (pm == pl) a = m; else c = m;
        }
        float b = __uint_as_float(a), bp = __uint_as_float(c);
        float ob, obp;
        uint32_t pb = snn_pat(b, one, &ob);
        uint32_t pbp = snn_pat(bp, one, &obp);

        int r = 0;  // rec 0 = exact-scan marker
        if (pb == pl && pbp == ph) {
            // [lo,b] uniform (oLo), [bp,hi] uniform (oHi): exact split.
            int slot = atomicAdd(&s_cnt, 1);
            if (slot < NREC) {
                g_rec[slot] = make_float4(b, oLo, oHi, 0.0f);
                r = slot;
            }
        }
        g_val[k] = __int_as_float(0x7FC00000u | (uint32_t)r);  // NaN-boxed idx
    }
}

static __device__ __forceinline__ float lut_val(float xv, const float* tbl, bool* bad) {
    float v0 = fabsf(xv);
    int idx = (int)(v0 * 2048.0f);   // exact (power-of-two scale), [0,4) range
    idx = min(idx, NCELL - 1);
    float val = tbl[idx];
    *bad |= !(val == val);
    return val;
}

static __device__ __forceinline__ void fix_rec(float* val, float xv,
                                               const float4* recs, bool* bad2) {
    if (!(*val == *val)) {
        uint32_t r = __float_as_uint(*val) & (NREC - 1);
        float4 rec = recs[r];
        float v0 = fabsf(xv);
        *val = (v0 > rec.x) ? rec.z : rec.y;
        *bad2 |= !(*val == *val);    // rec 0 -> still NaN -> exact scan
    }
}

static __device__ __forceinline__ float finish(float xv, float val) {
    // out = val * sign(x): XOR sign bit; exact 0 for x == 0.
    uint32_t rb = __float_as_uint(val) ^ (__float_as_uint(xv) & 0x80000000u);
    return (xv == 0.0f) ? 0.0f : __uint_as_float(rb);
}

__global__ void __launch_bounds__(256) Squre02_kernel(const float* __restrict__ x,
                                                      float* __restrict__ y, int n,
                                                      float one) {
    __shared__ __align__(16) float  tbl[NCELL];
    __shared__ __align__(16) float4 recs[NREC];
    {
        const float4* src = (const float4*)g_val;
        float4* dst = (float4*)tbl;
#pragma unroll
        for (int i = threadIdx.x; i < NCELL / 4; i += 256) dst[i] = src[i];
        if (threadIdx.x < NREC) recs[threadIdx.x] = g_rec[threadIdx.x];
    }
    __syncthreads();

    const int tid = blockIdx.x * blockDim.x + threadIdx.x;
    const int nthreads = gridDim.x * blockDim.x;
    const int n4 = n >> 2;
    const float4* __restrict__ x4 = (const float4*)x;
    float4* __restrict__ y4 = (float4*)y;

    for (int i = tid; i < n4; i += 2 * nthreads) {
        const int i2 = i + nthreads;
        const bool has2 = (i2 < n4);
        float4 a = __ldcs(&x4[i]);
        float4 b = has2 ? __ldcs(&x4[i2]) : make_float4(0.f, 0.f, 0.f, 0.f);

        bool bad = false;
        float va0 = lut_val(a.x, tbl, &bad);
        float va1 = lut_val(a.y, tbl, &bad);
        float va2 = lut_val(a.z, tbl, &bad);
        float va3 = lut_val(a.w, tbl, &bad);
        float vb0 = lut_val(b.x, tbl, &bad);
        float vb1 = lut_val(b.y, tbl, &bad);
        float vb2 = lut_val(b.z, tbl, &bad);
        float vb3 = lut_val(b.w, tbl, &bad);

        // Level 2: exact split records (rare: ~2% of lanes per slot).
        if (__ballot_sync(__activemask(), bad)) {
            bool bad2 = false;
            fix_rec(&va0, a.x, recs, &bad2);
            fix_rec(&va1, a.y, recs, &bad2);
            fix_rec(&va2, a.z, recs, &bad2);
            fix_rec(&va3, a.w, recs, &bad2);
            fix_rec(&vb0, b.x, recs, &bad2);
            fix_rec(&vb1, b.y, recs, &bad2);
            fix_rec(&vb2, b.z, recs, &bad2);
            fix_rec(&vb3, b.w, recs, &bad2);

            // Level 3: exact scan (rec 0 / overflow; ~never).
            if (__ballot_sync(__activemask(), bad2)) {
                if (!(va0 == va0)) va0 = snn_scan(fabsf(a.x), one);
                if (!(va1 == va1)) va1 = snn_scan(fabsf(a.y), one);
                if (!(va2 == va2)) va2 = snn_scan(fabsf(a.z), one);
                if (!(va3 == va3)) va3 = snn_scan(fabsf(a.w), one);
                if (!(vb0 == vb0)) vb0 = snn_scan(fabsf(b.x), one);
                if (!(vb1 == vb1)) vb1 = snn_scan(fabsf(b.y), one);
                if (!(vb2 == vb2)) vb2 = snn_scan(fabsf(b.z), one);
                if (!(vb3 == vb3)) vb3 = snn_scan(fabsf(b.w), one);
            }
        }

        float4 ra, rb;
        ra.x = finish(a.x, va0);
        ra.y = finish(a.y, va1);
        ra.z = finish(a.z, va2);
        ra.w = finish(a.w, va3);
        rb.x = finish(b.x, vb0);
        rb.y = finish(b.y, vb1);
        rb.z = finish(b.z, vb2);
        rb.w = finish(b.w, vb3);

        __stcs(&y4[i], ra);
        if (has2) __stcs(&y4[i2], rb);
    }

    // Scalar tail (not hit for this shape).
    for (int j = (n4 << 2) + tid; j < n; j += nthreads) {
        bool bad = false, bad2 = false;
        float v = lut_val(x[j], tbl, &bad);
        fix_rec(&v, x[j], recs, &bad2);
        if (!(v == v)) v = snn_scan(fabsf(x[j]), one);
        y[j] = finish(x[j], v);
    }
}

extern "C" void kernel_launch(void* const* d_in, const int* in_sizes, int n_in,
                              void* d_out, int out_size) {
    const float* x = (const float*)d_in[0];
    for (int i = 0; i < n_in; i++) {
        if (in_sizes[i] == out_size) { x = (const float*)d_in[i]; break; }
    }
    float* y = (float*)d_out;
    const int n = out_size;

    build_table<<<1, 1024>>>(1.0f);
    // 148 SMs x 6 CTAs (smem ~37KB/CTA -> 6 resident): balanced grid-stride.
    Squre02_kernel<<<888, 256>>>(x, y, n, 1.0f);
}